// round 1
// baseline (speedup 1.0000x reference)
#include <cuda_runtime.h>
#include <math.h>

// ---------------- problem constants ----------------
#define NB   4          // batch
#define CD   512        // channels / head dim
#define HW   4096       // h*w sequence length
#define TC   1536       // 3*C
#define NGRP 32
#define CPG  16         // channels per group
#define GSIZE (CPG*HW)  // 65536 elements per group (contiguous in NCHW)

// ---------------- device scratch (allocation-free) ----------------
__device__ float g_seq[(size_t)NB*HW*CD];        // 32 MB  (GN output, then reused for proj output)
__device__ float g_qkv[(size_t)NB*HW*TC];        // 100 MB
__device__ float g_scores[(size_t)NB*HW*HW];     // 256 MB
__device__ float g_attnout[(size_t)NB*HW*CD];    // 32 MB
__device__ float g_mean[NB*NGRP];
__device__ float g_rstd[NB*NGRP];

// ---------------- GroupNorm: stats ----------------
__global__ void gn_stats_kernel(const float* __restrict__ x) {
    int bg = blockIdx.x;                       // n*32+g, group data is contiguous
    const float* p = x + (size_t)bg * GSIZE;
    float s = 0.f, ss = 0.f;
    for (int i = threadIdx.x * 4; i < GSIZE; i += 256 * 4) {
        float4 v = *reinterpret_cast<const float4*>(p + i);
        s  += v.x + v.y + v.z + v.w;
        ss += v.x*v.x + v.y*v.y + v.z*v.z + v.w*v.w;
    }
    __shared__ float rs[256], rq[256];
    rs[threadIdx.x] = s; rq[threadIdx.x] = ss;
    __syncthreads();
    for (int o = 128; o > 0; o >>= 1) {
        if (threadIdx.x < o) { rs[threadIdx.x] += rs[threadIdx.x+o]; rq[threadIdx.x] += rq[threadIdx.x+o]; }
        __syncthreads();
    }
    if (threadIdx.x == 0) {
        float m   = rs[0] * (1.0f / GSIZE);
        float var = rq[0] * (1.0f / GSIZE) - m * m;
        g_mean[bg] = m;
        g_rstd[bg] = rsqrtf(var + 1e-5f);
    }
}

// ---------------- GroupNorm apply + NCHW -> (n, s, c) transpose ----------------
__global__ void gn_apply_kernel(const float* __restrict__ x,
                                const float* __restrict__ gscale,
                                const float* __restrict__ gbias) {
    __shared__ float tile[32][33];
    int n  = blockIdx.z;
    int c0 = blockIdx.y * 32;
    int s0 = blockIdx.x * 32;
    int tx = threadIdx.x, ty = threadIdx.y;     // (32, 8)
    #pragma unroll
    for (int i = ty; i < 32; i += 8) {
        int c = c0 + i;
        int gidx = n * NGRP + (c >> 4);
        float m = g_mean[gidx], r = g_rstd[gidx];
        float v = x[((size_t)(n * CD + c)) * HW + s0 + tx];
        tile[i][tx] = (v - m) * r * gscale[c] + gbias[c];
    }
    __syncthreads();
    #pragma unroll
    for (int i = ty; i < 32; i += 8) {
        g_seq[((size_t)(n * HW + s0 + i)) * CD + c0 + tx] = tile[tx][i];
    }
}

// ---------------- generic SGEMM: C = alpha * A * op(B) (+ bias) ----------------
// A: [M,K] row-major (lda), TRANS_B ? B:[N,K] (ldb) : B:[K,N] (ldb)
// Tiles: 128x128x8, 256 threads, 8x8 per-thread (split 4+4 to avoid LDS conflicts).
// All M,N multiples of 128; K multiple of 8. No bounds checks needed.
template<bool TRANS_B, bool HAS_BIAS>
__global__ __launch_bounds__(256, 2)
void sgemm_kernel(const float* __restrict__ Ag, int lda, long sA,
                  const float* __restrict__ Bg, int ldb, long sB,
                  float* __restrict__ Cg, int ldc, long sC,
                  int K, float alpha, const float* __restrict__ bias) {
    __shared__ float As[8][132];
    __shared__ float Bs[8][132];

    const float* A = Ag + (size_t)blockIdx.z * sA;
    const float* B = Bg + (size_t)blockIdx.z * sB;
    float*       C = Cg + (size_t)blockIdx.z * sC;

    const int brow = blockIdx.y * 128;
    const int bcol = blockIdx.x * 128;
    const int tid  = threadIdx.x;
    const int tx   = tid & 15;
    const int ty   = tid >> 4;

    const int a_row = tid >> 1;           // 0..127
    const int a_k   = (tid & 1) * 4;      // 0 or 4
    const int bn_k  = tid >> 5;           // 0..7   (!TRANS_B path)
    const int bn_col= (tid & 31) * 4;     // 0..124

    float acc[8][8];
    #pragma unroll
    for (int i = 0; i < 8; i++)
        #pragma unroll
        for (int j = 0; j < 8; j++) acc[i][j] = 0.f;

    const float* Aptr = A + (size_t)(brow + a_row) * lda + a_k;
    const float* Bptr = TRANS_B ? (B + (size_t)(bcol + a_row) * ldb + a_k)
                                : (B + (size_t)bn_k * ldb + bcol + bn_col);

    for (int k0 = 0; k0 < K; k0 += 8) {
        float4 av = *reinterpret_cast<const float4*>(Aptr); Aptr += 8;
        As[a_k+0][a_row] = av.x; As[a_k+1][a_row] = av.y;
        As[a_k+2][a_row] = av.z; As[a_k+3][a_row] = av.w;
        if (TRANS_B) {
            float4 bv = *reinterpret_cast<const float4*>(Bptr); Bptr += 8;
            Bs[a_k+0][a_row] = bv.x; Bs[a_k+1][a_row] = bv.y;
            Bs[a_k+2][a_row] = bv.z; Bs[a_k+3][a_row] = bv.w;
        } else {
            float4 bv = *reinterpret_cast<const float4*>(Bptr); Bptr += (size_t)8 * ldb;
            *reinterpret_cast<float4*>(&Bs[bn_k][bn_col]) = bv;
        }
        __syncthreads();
        #pragma unroll
        for (int kk = 0; kk < 8; kk++) {
            float ar[8], br[8];
            #pragma unroll
            for (int i = 0; i < 4; i++) { ar[i] = As[kk][ty*4 + i]; ar[i+4] = As[kk][64 + ty*4 + i]; }
            #pragma unroll
            for (int j = 0; j < 4; j++) { br[j] = Bs[kk][tx*4 + j]; br[j+4] = Bs[kk][64 + tx*4 + j]; }
            #pragma unroll
            for (int i = 0; i < 8; i++)
                #pragma unroll
                for (int j = 0; j < 8; j++)
                    acc[i][j] = fmaf(ar[i], br[j], acc[i][j]);
        }
        __syncthreads();
    }

    #pragma unroll
    for (int i = 0; i < 8; i++) {
        int row = brow + ((i < 4) ? (ty*4 + i) : (64 + ty*4 + (i - 4)));
        #pragma unroll
        for (int jc = 0; jc < 2; jc++) {
            int col = bcol + ((jc == 0) ? (tx*4) : (64 + tx*4));
            float4 v;
            v.x = acc[i][jc*4+0] * alpha;
            v.y = acc[i][jc*4+1] * alpha;
            v.z = acc[i][jc*4+2] * alpha;
            v.w = acc[i][jc*4+3] * alpha;
            if (HAS_BIAS) {
                v.x += bias[col+0]; v.y += bias[col+1];
                v.z += bias[col+2]; v.w += bias[col+3];
            }
            *reinterpret_cast<float4*>(&C[(size_t)row * ldc + col]) = v;
        }
    }
}

// ---------------- row softmax over g_scores (rows of length 4096) ----------------
__global__ void softmax_kernel() {
    float* row = g_scores + (size_t)blockIdx.x * HW;
    int tid = threadIdx.x;
    float4 v[4];
    float mx = -1e30f;
    #pragma unroll
    for (int j = 0; j < 4; j++) {
        v[j] = *reinterpret_cast<const float4*>(row + tid*4 + j*1024);
        mx = fmaxf(mx, fmaxf(fmaxf(v[j].x, v[j].y), fmaxf(v[j].z, v[j].w)));
    }
    __shared__ float red[256];
    red[tid] = mx; __syncthreads();
    for (int o = 128; o > 0; o >>= 1) {
        if (tid < o) red[tid] = fmaxf(red[tid], red[tid+o]);
        __syncthreads();
    }
    mx = red[0];
    __syncthreads();
    float s = 0.f;
    #pragma unroll
    for (int j = 0; j < 4; j++) {
        v[j].x = expf(v[j].x - mx); v[j].y = expf(v[j].y - mx);
        v[j].z = expf(v[j].z - mx); v[j].w = expf(v[j].w - mx);
        s += v[j].x + v[j].y + v[j].z + v[j].w;
    }
    red[tid] = s; __syncthreads();
    for (int o = 128; o > 0; o >>= 1) {
        if (tid < o) red[tid] += red[tid+o];
        __syncthreads();
    }
    float inv = 1.f / red[0];
    #pragma unroll
    for (int j = 0; j < 4; j++) {
        v[j].x *= inv; v[j].y *= inv; v[j].z *= inv; v[j].w *= inv;
        *reinterpret_cast<float4*>(row + tid*4 + j*1024) = v[j];
    }
}

// ---------------- (n,s,c) -> NCHW transpose + residual add ----------------
__global__ void out_transpose_kernel(const float* __restrict__ x, float* __restrict__ out) {
    __shared__ float tile[32][33];
    int n  = blockIdx.z;
    int c0 = blockIdx.y * 32;
    int s0 = blockIdx.x * 32;
    int tx = threadIdx.x, ty = threadIdx.y;   // (32, 8)
    #pragma unroll
    for (int i = ty; i < 32; i += 8)
        tile[i][tx] = g_seq[((size_t)(n * HW + s0 + i)) * CD + c0 + tx];
    __syncthreads();
    #pragma unroll
    for (int i = ty; i < 32; i += 8) {
        size_t idx = ((size_t)(n * CD + c0 + i)) * HW + s0 + tx;
        out[idx] = tile[tx][i] + x[idx];
    }
}

// ---------------- launcher ----------------
extern "C" void kernel_launch(void* const* d_in, const int* in_sizes, int n_in,
                              void* d_out, int out_size) {
    const float* x        = (const float*)d_in[0];
    const float* gn_scale = (const float*)d_in[1];
    const float* gn_bias  = (const float*)d_in[2];
    const float* w_in     = (const float*)d_in[3];
    const float* b_in     = (const float*)d_in[4];
    const float* w_out    = (const float*)d_in[5];
    const float* b_out    = (const float*)d_in[6];
    float* out = (float*)d_out;

    float *seq, *qkv, *scores, *attnout;
    cudaGetSymbolAddress((void**)&seq,     g_seq);
    cudaGetSymbolAddress((void**)&qkv,     g_qkv);
    cudaGetSymbolAddress((void**)&scores,  g_scores);
    cudaGetSymbolAddress((void**)&attnout, g_attnout);

    // 1) GroupNorm stats + apply/transpose -> g_seq [n, hw, c]
    gn_stats_kernel<<<NB * NGRP, 256>>>(x);
    dim3 tb(32, 8);
    gn_apply_kernel<<<dim3(HW/32, CD/32, NB), tb>>>(x, gn_scale, gn_bias);

    // 2) QKV: [16384,512] x w_in^T[512,1536] -> g_qkv [n, hw, 3c]
    sgemm_kernel<true, true><<<dim3(TC/128, (NB*HW)/128, 1), 256>>>(
        seq, CD, 0, w_in, CD, 0, qkv, TC, 0, CD, 1.0f, b_in);

    // 3) scores = Q K^T * 1/sqrt(512)   (per batch)
    const float scale = 0.044194173824159216f;  // 1/sqrt(512)
    sgemm_kernel<true, false><<<dim3(HW/128, HW/128, NB), 256>>>(
        qkv, TC, (long)HW*TC, qkv + 512, TC, (long)HW*TC,
        scores, HW, (long)HW*HW, CD, scale, nullptr);

    // 4) softmax over rows
    softmax_kernel<<<NB * HW, 256>>>();

    // 5) attnout = attn V   (B non-transposed: V is [t, d] with row stride 1536)
    sgemm_kernel<false, false><<<dim3(CD/128, HW/128, NB), 256>>>(
        scores, HW, (long)HW*HW, qkv + 1024, TC, (long)HW*TC,
        attnout, CD, (long)HW*CD, HW, 1.0f, nullptr);

    // 6) out-proj: attnout x w_out^T + b_out  -> reuse g_seq
    sgemm_kernel<true, true><<<dim3(CD/128, (NB*HW)/128, 1), 256>>>(
        attnout, CD, 0, w_out, CD, 0, seq, CD, 0, CD, 1.0f, b_out);

    // 7) transpose back to NCHW + residual
    out_transpose_kernel<<<dim3(HW/32, CD/32, NB), tb>>>(x, out);
}

// round 7
// speedup vs baseline: 1.9215x; 1.9215x over previous
#include <cuda_runtime.h>
#include <cuda_bf16.h>
#include <cstdint>
#include <math.h>

// ---------------- problem constants ----------------
#define NB   4
#define CD   512
#define HW   4096
#define TC   1536
#define NGRP 32
#define GSIZE (16*HW)

// ---------------- device scratch (allocation-free) ----------------
__device__ float g_seq[(size_t)NB*HW*CD];
__device__ float g_qkv[(size_t)NB*HW*TC];
__device__ float g_scores[(size_t)NB*HW*HW];
__device__ float g_attnout[(size_t)NB*HW*CD];
__device__ float g_vt[(size_t)NB*CD*HW];
__device__ float g_mean[NB*NGRP];
__device__ float g_rstd[NB*NGRP];

// ---------------- helpers ----------------
static __device__ __forceinline__ uint32_t smem_u32(const void* p) {
    uint32_t a;
    asm("{ .reg .u64 t; cvta.to.shared.u64 t, %1; cvt.u32.u64 %0, t; }" : "=r"(a) : "l"(p));
    return a;
}
static __device__ __forceinline__ void mma_bf16(float* c, const uint32_t* a, const uint32_t* b) {
    asm volatile(
        "mma.sync.aligned.m16n8k16.row.col.f32.bf16.bf16.f32 "
        "{%0,%1,%2,%3}, {%4,%5,%6,%7}, {%8,%9}, {%0,%1,%2,%3};"
        : "+f"(c[0]), "+f"(c[1]), "+f"(c[2]), "+f"(c[3])
        : "r"(a[0]), "r"(a[1]), "r"(a[2]), "r"(a[3]), "r"(b[0]), "r"(b[1]));
}
static __device__ __forceinline__ void ldsm4(uint32_t* r, uint32_t addr) {
    asm volatile("ldmatrix.sync.aligned.m8n8.x4.shared.b16 {%0,%1,%2,%3}, [%4];"
                 : "=r"(r[0]), "=r"(r[1]), "=r"(r[2]), "=r"(r[3]) : "r"(addr));
}
static __device__ __forceinline__ void split_pack(float f0, float f1, uint32_t& hi, uint32_t& lo) {
    __nv_bfloat162 h = __floats2bfloat162_rn(f0, f1);
    float l0 = f0 - __bfloat162float(h.x);
    float l1 = f1 - __bfloat162float(h.y);
    __nv_bfloat162 l = __floats2bfloat162_rn(l0, l1);
    hi = *reinterpret_cast<uint32_t*>(&h);
    lo = *reinterpret_cast<uint32_t*>(&l);
}

// SMEM: per stage 4 matrices (Ah, Al, Bh, Bl), each 128 rows x 12 words (8 data + 4 pad).
#define PITCH 12
#define MATW  (128*PITCH)     // 1536 words per matrix
#define STW   (4*MATW)        // 6144 words per stage
// total static smem = 2*STW*4 = 49152 bytes (exactly the 48KB static limit)

// ---------------- bf16-split tensor GEMM: C = alpha * A * B^T (+bias) ----------------
// A: [M,K] row-major (lda), B: [N,K] row-major (ldb), C: [M,N] (ldc).
// M,N multiples of 128, K multiple of 16. 512 threads, 16 warps 4(M)x4(N),
// warp tile 32x32: 2 m16-tiles x 4 n8-tiles, k16 chunks, 3 bf16 products each.
template<bool HAS_BIAS>
__global__ __launch_bounds__(512, 1)
void mma_gemm(const float* __restrict__ Ag, int lda, long long sA,
              const float* __restrict__ Bg, int ldb, long long sB,
              float* __restrict__ Cg, int ldc, long long sC,
              int K, float alpha, const float* __restrict__ bias)
{
    __shared__ uint32_t sm[2*STW];
    const uint32_t smb = smem_u32(sm);

    const int tid  = threadIdx.x;
    const int lane = tid & 31;
    const int wid  = tid >> 5;        // 0..15
    const int wm   = wid >> 2;        // 0..3
    const int wn   = wid & 3;         // 0..3
    const int tq   = lane >> 2;       // 0..7
    const int tr   = lane & 3;        // 0..3

    const float* A = Ag + (size_t)blockIdx.z * sA + (size_t)(blockIdx.y * 128) * lda;
    const float* B = Bg + (size_t)blockIdx.z * sB + (size_t)(blockIdx.x * 128) * ldb;

    // ldmatrix per-lane addressing: 4 phases of 8 rows
    const int lrow = ((lane >> 3) & 1) * 8 + (lane & 7);
    const int lkw  = (lane >> 4) * 4;
    uint32_t a_ad[2], b_ad[2];
    #pragma unroll
    for (int mt = 0; mt < 2; mt++)
        a_ad[mt] = smb + (uint32_t)(((wm*32 + mt*16 + lrow) * PITCH + lkw) * 4);
    #pragma unroll
    for (int p = 0; p < 2; p++)
        b_ad[p]  = smb + (uint32_t)(((wn*32 + p*16 + lrow) * PITCH + lkw) * 4);

    // staging: each thread loads one float4 of A and one of B per chunk
    const int grow = tid >> 2;          // 0..127
    const int gc   = (tid & 3) * 4;     // float col 0,4,8,12
    const int wo   = grow * PITCH + (tid & 3) * 2;

    float acc[8][4];
    #pragma unroll
    for (int i = 0; i < 8; i++) { acc[i][0]=0.f; acc[i][1]=0.f; acc[i][2]=0.f; acc[i][3]=0.f; }

    const int nch = K >> 4;
    float4 rA, rB;

    // prologue: chunk 0 -> stage 0
    rA = *reinterpret_cast<const float4*>(A + (size_t)grow * lda + gc);
    rB = *reinterpret_cast<const float4*>(B + (size_t)grow * ldb + gc);
    {
        uint32_t h0,l0,h1,l1;
        split_pack(rA.x, rA.y, h0, l0); split_pack(rA.z, rA.w, h1, l1);
        sm[wo] = h0; sm[wo+1] = h1; sm[MATW+wo] = l0; sm[MATW+wo+1] = l1;
        split_pack(rB.x, rB.y, h0, l0); split_pack(rB.z, rB.w, h1, l1);
        sm[2*MATW+wo] = h0; sm[2*MATW+wo+1] = h1; sm[3*MATW+wo] = l0; sm[3*MATW+wo+1] = l1;
    }
    __syncthreads();

    for (int kc = 0; kc < nch; kc++) {
        if (kc + 1 < nch) {
            rA = *reinterpret_cast<const float4*>(A + (size_t)grow * lda + (kc+1)*16 + gc);
            rB = *reinterpret_cast<const float4*>(B + (size_t)grow * ldb + (kc+1)*16 + gc);
        }

        const uint32_t sbase = (uint32_t)((kc & 1) * STW * 4);
        uint32_t ah[2][4], al[2][4], bh[4][2], bl[4][2];
        #pragma unroll
        for (int mt = 0; mt < 2; mt++) {
            ldsm4(ah[mt], a_ad[mt] + sbase);
            ldsm4(al[mt], a_ad[mt] + sbase + MATW*4);
        }
        #pragma unroll
        for (int p = 0; p < 2; p++) {
            uint32_t r[4];
            ldsm4(r, b_ad[p] + sbase + 2*MATW*4);
            bh[p*2][0] = r[0]; bh[p*2+1][0] = r[1]; bh[p*2][1] = r[2]; bh[p*2+1][1] = r[3];
            ldsm4(r, b_ad[p] + sbase + 3*MATW*4);
            bl[p*2][0] = r[0]; bl[p*2+1][0] = r[1]; bl[p*2][1] = r[2]; bl[p*2+1][1] = r[3];
        }

        #pragma unroll
        for (int mt = 0; mt < 2; mt++)
            #pragma unroll
            for (int nt = 0; nt < 4; nt++) mma_bf16(acc[mt*4+nt], ah[mt], bh[nt]);
        #pragma unroll
        for (int mt = 0; mt < 2; mt++)
            #pragma unroll
            for (int nt = 0; nt < 4; nt++) mma_bf16(acc[mt*4+nt], ah[mt], bl[nt]);
        #pragma unroll
        for (int mt = 0; mt < 2; mt++)
            #pragma unroll
            for (int nt = 0; nt < 4; nt++) mma_bf16(acc[mt*4+nt], al[mt], bh[nt]);

        if (kc + 1 < nch) {
            uint32_t* s1 = sm + ((kc + 1) & 1) * STW;
            uint32_t h0,l0,h1,l1;
            split_pack(rA.x, rA.y, h0, l0); split_pack(rA.z, rA.w, h1, l1);
            s1[wo] = h0; s1[wo+1] = h1; s1[MATW+wo] = l0; s1[MATW+wo+1] = l1;
            split_pack(rB.x, rB.y, h0, l0); split_pack(rB.z, rB.w, h1, l1);
            s1[2*MATW+wo] = h0; s1[2*MATW+wo+1] = h1; s1[3*MATW+wo] = l0; s1[3*MATW+wo+1] = l1;
        }
        __syncthreads();
    }

    // epilogue
    float* C = Cg + (size_t)blockIdx.z * sC;
    #pragma unroll
    for (int mt = 0; mt < 2; mt++) {
        int row0 = blockIdx.y * 128 + wm * 32 + mt * 16 + tq;
        #pragma unroll
        for (int nt = 0; nt < 4; nt++) {
            int col = blockIdx.x * 128 + wn * 32 + nt * 8 + tr * 2;
            float b0 = 0.f, b1 = 0.f;
            if (HAS_BIAS) { b0 = bias[col]; b1 = bias[col + 1]; }
            float2 v0 = make_float2(acc[mt*4+nt][0] * alpha + b0, acc[mt*4+nt][1] * alpha + b1);
            float2 v1 = make_float2(acc[mt*4+nt][2] * alpha + b0, acc[mt*4+nt][3] * alpha + b1);
            *reinterpret_cast<float2*>(C + (size_t)row0 * ldc + col)       = v0;
            *reinterpret_cast<float2*>(C + (size_t)(row0 + 8) * ldc + col) = v1;
        }
    }
}

// ---------------- GroupNorm stats ----------------
__global__ void gn_stats_kernel(const float* __restrict__ x) {
    int bg = blockIdx.x;
    const float* p = x + (size_t)bg * GSIZE;
    float s = 0.f, ss = 0.f;
    for (int i = threadIdx.x * 4; i < GSIZE; i += 256 * 4) {
        float4 v = *reinterpret_cast<const float4*>(p + i);
        s  += v.x + v.y + v.z + v.w;
        ss += v.x*v.x + v.y*v.y + v.z*v.z + v.w*v.w;
    }
    __shared__ float rs[256], rq[256];
    rs[threadIdx.x] = s; rq[threadIdx.x] = ss;
    __syncthreads();
    for (int o = 128; o > 0; o >>= 1) {
        if (threadIdx.x < o) { rs[threadIdx.x] += rs[threadIdx.x+o]; rq[threadIdx.x] += rq[threadIdx.x+o]; }
        __syncthreads();
    }
    if (threadIdx.x == 0) {
        float m   = rs[0] * (1.0f / GSIZE);
        float var = rq[0] * (1.0f / GSIZE) - m * m;
        g_mean[bg] = m;
        g_rstd[bg] = rsqrtf(var + 1e-5f);
    }
}

// ---------------- GroupNorm apply + NCHW -> (n,s,c) ----------------
__global__ void gn_apply_kernel(const float* __restrict__ x,
                                const float* __restrict__ gscale,
                                const float* __restrict__ gbias) {
    __shared__ float tile[32][33];
    int n  = blockIdx.z;
    int c0 = blockIdx.y * 32;
    int s0 = blockIdx.x * 32;
    int tx = threadIdx.x, ty = threadIdx.y;
    #pragma unroll
    for (int i = ty; i < 32; i += 8) {
        int c = c0 + i;
        int gidx = n * NGRP + (c >> 4);
        float m = g_mean[gidx], r = g_rstd[gidx];
        float v = x[((size_t)(n * CD + c)) * HW + s0 + tx];
        tile[i][tx] = (v - m) * r * gscale[c] + gbias[c];
    }
    __syncthreads();
    #pragma unroll
    for (int i = ty; i < 32; i += 8)
        g_seq[((size_t)(n * HW + s0 + i)) * CD + c0 + tx] = tile[tx][i];
}

// ---------------- V transpose: qkv V part [t,d] -> g_vt [d,t] ----------------
__global__ void v_transpose_kernel() {
    __shared__ float tile[32][33];
    int n  = blockIdx.z;
    int d0 = blockIdx.y * 32;
    int t0 = blockIdx.x * 32;
    int tx = threadIdx.x, ty = threadIdx.y;
    #pragma unroll
    for (int i = ty; i < 32; i += 8)
        tile[i][tx] = g_qkv[((size_t)(n * HW + t0 + i)) * TC + 1024 + d0 + tx];
    __syncthreads();
    #pragma unroll
    for (int i = ty; i < 32; i += 8)
        g_vt[((size_t)(n * CD + d0 + i)) * HW + t0 + tx] = tile[tx][i];
}

// ---------------- row softmax on g_scores ----------------
__global__ void softmax_kernel() {
    float* row = g_scores + (size_t)blockIdx.x * HW;
    int tid = threadIdx.x;
    float4 v[4];
    float mx = -1e30f;
    #pragma unroll
    for (int j = 0; j < 4; j++) {
        v[j] = *reinterpret_cast<const float4*>(row + tid*4 + j*1024);
        mx = fmaxf(mx, fmaxf(fmaxf(v[j].x, v[j].y), fmaxf(v[j].z, v[j].w)));
    }
    __shared__ float red[256];
    red[tid] = mx; __syncthreads();
    for (int o = 128; o > 0; o >>= 1) {
        if (tid < o) red[tid] = fmaxf(red[tid], red[tid+o]);
        __syncthreads();
    }
    mx = red[0];
    __syncthreads();
    float s = 0.f;
    #pragma unroll
    for (int j = 0; j < 4; j++) {
        v[j].x = expf(v[j].x - mx); v[j].y = expf(v[j].y - mx);
        v[j].z = expf(v[j].z - mx); v[j].w = expf(v[j].w - mx);
        s += v[j].x + v[j].y + v[j].z + v[j].w;
    }
    red[tid] = s; __syncthreads();
    for (int o = 128; o > 0; o >>= 1) {
        if (tid < o) red[tid] += red[tid+o];
        __syncthreads();
    }
    float inv = 1.f / red[0];
    #pragma unroll
    for (int j = 0; j < 4; j++) {
        v[j].x *= inv; v[j].y *= inv; v[j].z *= inv; v[j].w *= inv;
        *reinterpret_cast<float4*>(row + tid*4 + j*1024) = v[j];
    }
}

// ---------------- (n,s,c) -> NCHW + residual ----------------
__global__ void out_transpose_kernel(const float* __restrict__ x, float* __restrict__ out) {
    __shared__ float tile[32][33];
    int n  = blockIdx.z;
    int c0 = blockIdx.y * 32;
    int s0 = blockIdx.x * 32;
    int tx = threadIdx.x, ty = threadIdx.y;
    #pragma unroll
    for (int i = ty; i < 32; i += 8)
        tile[i][tx] = g_seq[((size_t)(n * HW + s0 + i)) * CD + c0 + tx];
    __syncthreads();
    #pragma unroll
    for (int i = ty; i < 32; i += 8) {
        size_t idx = ((size_t)(n * CD + c0 + i)) * HW + s0 + tx;
        out[idx] = tile[tx][i] + x[idx];
    }
}

// ---------------- launcher ----------------
extern "C" void kernel_launch(void* const* d_in, const int* in_sizes, int n_in,
                              void* d_out, int out_size) {
    const float* x        = (const float*)d_in[0];
    const float* gn_scale = (const float*)d_in[1];
    const float* gn_bias  = (const float*)d_in[2];
    const float* w_in     = (const float*)d_in[3];
    const float* b_in     = (const float*)d_in[4];
    const float* w_out    = (const float*)d_in[5];
    const float* b_out    = (const float*)d_in[6];
    float* out = (float*)d_out;

    float *seq, *qkv, *scores, *attnout, *vt;
    cudaGetSymbolAddress((void**)&seq,     g_seq);
    cudaGetSymbolAddress((void**)&qkv,     g_qkv);
    cudaGetSymbolAddress((void**)&scores,  g_scores);
    cudaGetSymbolAddress((void**)&attnout, g_attnout);
    cudaGetSymbolAddress((void**)&vt,      g_vt);

    dim3 tb(32, 8);

    // 1) GroupNorm
    gn_stats_kernel<<<NB * NGRP, 256>>>(x);
    gn_apply_kernel<<<dim3(HW/32, CD/32, NB), tb>>>(x, gn_scale, gn_bias);

    // 2) QKV: [16384,512] x w_in[1536,512]^T -> g_qkv
    mma_gemm<true><<<dim3(TC/128, (NB*HW)/128, 1), 512>>>(
        seq, CD, 0LL, w_in, CD, 0LL, qkv, TC, 0LL, CD, 1.0f, b_in);

    // 3) V transpose
    v_transpose_kernel<<<dim3(HW/32, CD/32, NB), tb>>>();

    // 4) scores = Q K^T / sqrt(512)
    mma_gemm<false><<<dim3(HW/128, HW/128, NB), 512>>>(
        qkv, TC, (long long)HW*TC, qkv + 512, TC, (long long)HW*TC,
        scores, HW, (long long)HW*HW, CD, 0.044194173824159216f, nullptr);

    // 5) softmax
    softmax_kernel<<<NB * HW, 256>>>();

    // 6) attnout = attn * V   (B = Vt[d][t], K-major over t)
    mma_gemm<false><<<dim3(CD/128, HW/128, NB), 512>>>(
        scores, HW, (long long)HW*HW, vt, HW, (long long)CD*HW,
        attnout, CD, (long long)HW*CD, HW, 1.0f, nullptr);

    // 7) out-proj -> g_seq
    mma_gemm<true><<<dim3(CD/128, (NB*HW)/128, 1), 512>>>(
        attnout, CD, 0LL, w_out, CD, 0LL, seq, CD, 0LL, CD, 1.0f, b_out);

    // 8) transpose back + residual
    out_transpose_kernel<<<dim3(HW/32, CD/32, NB), tb>>>(x, out);
}